// round 13
// baseline (speedup 1.0000x reference)
#include <cuda_runtime.h>
#include <cuda_fp16.h>

// Problem shape (fixed by the dataset)
#define BATCH 8
#define CHAN  3
#define HH    720
#define WW    1280
#define HW    (HH * WW)
#define NROWS (BATCH * HH)
#define ROWS_PB 4
#define EPSV  1e-6f
#define K_LOG2 0.49978218f     // log2(1.414)

// flow_y == 0 -> 1-D row splat: pixel x hits bins x0=floor(x-d) and x0+1.
// (c0,c1) and (c2,wsum) accumulate as two __half2 shared planes via
// return-free red.shared.add.noftz.f16x2. 4 REDs/pixel is the exact payload
// floor (8 f16 scalars / 2 per 32-bit RED); RED lane rate (~2.3 lanes/cyc/SM)
// pins l1tex busy at ~46us.
//
// R13: 4 rows per block, sequential loop, double-buffered planes. The next
// row's zero phase overlaps the current row's splat (no zero->splat
// serialization); grid drops 5760 -> 1440 (fewer wave tails). launch_bounds
// (320,6) pins 6 CTAs/SM (R11's unrolled variant lost occupancy to regs).
__device__ __forceinline__ int bhash(int bin) {
    return bin ^ ((bin >> 5) & 28);
}

__device__ __forceinline__ void red_sh_h2(unsigned addr, unsigned val) {
    asm volatile("red.shared.add.noftz.f16x2 [%0], %1;"
                 :: "r"(addr), "r"(val) : "memory");
}

__device__ __forceinline__ unsigned pack_h2(float a, float b) {
    __half2 h = __floats2half2_rn(a, b);
    return *(unsigned*)&h;
}

// splat one pixel: compute payloads and fire up to 4 REDs
__device__ __forceinline__ void splat_px(
    int x, float d, float v0, float v1, float v2,
    unsigned baseA, unsigned baseB)
{
    float w;
    asm("ex2.approx.f32 %0, %1;" : "=f"(w) : "f"(d * K_LOG2));
    float tx  = (float)x - d;
    int   x0  = __float2int_rd(tx);
    float fc  = tx - (float)x0;   // weight toward x0+1
    float wc  = w * fc;           // combined weight at x0+1
    float wa  = w - wc;           // combined weight at x0

    if ((unsigned)x0 < WW) {      // x0 in [x-21, x]
        unsigned h0 = 4u * bhash(x0);
        red_sh_h2(baseA + h0, pack_h2(v0 * wa, v1 * wa));
        red_sh_h2(baseB + h0, pack_h2(v2 * wa, wa));
    }
    int x1 = x0 + 1;
    if ((unsigned)x1 < WW) {
        unsigned h1 = 4u * bhash(x1);
        red_sh_h2(baseA + h1, pack_h2(v0 * wc, v1 * wc));
        red_sh_h2(baseB + h1, pack_h2(v2 * wc, wc));
    }
}

__global__ __launch_bounds__(320, 6) void splat_kernel(
    const float* __restrict__ im,
    const float* __restrict__ disp,
    float* __restrict__ out)
{
    __shared__ __half2 sA[2][WW];   // (c0, c1), hashed slots, double-buffered
    __shared__ __half2 sB[2][WW];   // (c2, w ), hashed slots, double-buffered

    const int row0 = blockIdx.x * ROWS_PB;   // HH%4==0 -> same batch
    const int b    = row0 / HH;
    const int y0   = row0 - b * HH;
    const int tid  = threadIdx.x;
    const int xb   = tid * 4;

    const float* im_b = im  + (size_t)b * CHAN * HW;
    float*       o_b  = out + (size_t)b * CHAN * HW;

    // preloop: zero buffer 0
    {
        uint4 z = make_uint4(0u, 0u, 0u, 0u);
        ((uint4*)sA[0])[tid] = z;
        ((uint4*)sB[0])[tid] = z;
    }
    __syncthreads();

    #pragma unroll 1
    for (int r = 0; r < ROWS_PB; r++) {
        const int p = r & 1;
        const int y = y0 + r;
        const unsigned baseA = (unsigned)__cvta_generic_to_shared(sA[p]);
        const unsigned baseB = (unsigned)__cvta_generic_to_shared(sB[p]);

        const float4* d_row4 = (const float4*)(disp + (size_t)(row0 + r) * WW);
        const float*  im_row = im_b + (size_t)y * WW;

        float4 d4 = d_row4[tid];
        float4 c0 = ((const float4*)(im_row))[tid];
        float4 c1 = ((const float4*)(im_row + HW))[tid];
        float4 c2 = ((const float4*)(im_row + 2 * HW))[tid];

        splat_px(xb,     d4.x, c0.x, c1.x, c2.x, baseA, baseB);
        splat_px(xb + 1, d4.y, c0.y, c1.y, c2.y, baseA, baseB);
        splat_px(xb + 2, d4.z, c0.z, c1.z, c2.z, baseA, baseB);
        splat_px(xb + 3, d4.w, c0.w, c1.w, c2.w, baseA, baseB);

        // overlap: zero the other buffer for row r+1 (no sync needed before
        // it — next splat into it only begins after the barrier below)
        if (r + 1 < ROWS_PB) {
            uint4 z = make_uint4(0u, 0u, 0u, 0u);
            ((uint4*)sA[p ^ 1])[tid] = z;
            ((uint4*)sB[p ^ 1])[tid] = z;
        }
        __syncthreads();

        // ---- normalize row r from buffer p ----
        const int g = (xb ^ ((xb >> 5) & 28)) >> 2;
        uint4 ua = ((const uint4*)sA[p])[g];
        uint4 ub = ((const uint4*)sB[p])[g];
        const unsigned va[4] = {ua.x, ua.y, ua.z, ua.w};
        const unsigned vb[4] = {ub.x, ub.y, ub.z, ub.w};

        float* o_row = o_b + (size_t)y * WW;
        float4 r0, r1, r2;
        float* r0p = &r0.x; float* r1p = &r1.x; float* r2p = &r2.x;
        #pragma unroll
        for (int j = 0; j < 4; j++) {
            __half2 a  = *(const __half2*)&va[j];
            __half2 bb = *(const __half2*)&vb[j];
            float n0 = __low2float(a),  n1 = __high2float(a);
            float n2 = __low2float(bb), ws = __high2float(bb);
            float inv;
            asm("rcp.approx.f32 %0, %1;" : "=f"(inv) : "f"(fmaxf(ws, EPSV)));
            r0p[j] = n0 * inv;
            r1p[j] = n1 * inv;
            r2p[j] = n2 * inv;
        }
        ((float4*)o_row)[tid]            = r0;
        ((float4*)(o_row + HW))[tid]     = r1;
        ((float4*)(o_row + 2 * HW))[tid] = r2;

        // normalize reads of buffer p must finish before iteration r+2
        // re-zeroes... (r+1 zeroes p only at its overlap step, which races
        // with nothing: p is splat target again only in r+2). This barrier
        // orders normalize reads before the NEXT iteration's zero of p^1?
        // p^1 was just zeroed above; next iteration splats into it. The
        // barrier orders this iteration's zero+normalize against the next
        // iteration's REDs and zero of buffer p.
        __syncthreads();
    }
}

extern "C" void kernel_launch(void* const* d_in, const int* in_sizes, int n_in,
                              void* d_out, int out_size) {
    const float* im   = (const float*)d_in[0];   // [8,3,720,1280] fp32
    const float* disp = (const float*)d_in[1];   // [8,1,720,1280] fp32
    float* out = (float*)d_out;                  // [8,3,720,1280] fp32

    splat_kernel<<<NROWS / ROWS_PB, 320>>>(im, disp, out);
}

// round 14
// speedup vs baseline: 1.0038x; 1.0038x over previous
#include <cuda_runtime.h>
#include <cuda_fp16.h>

// Problem shape (fixed by the dataset)
#define BATCH 8
#define CHAN  3
#define HH    720
#define WW    1280
#define HW    (HH * WW)
#define NROWS (BATCH * HH)
#define GRID  888            // 148 SMs * 6 CTAs: exactly one wave
#define EPSV  1e-6f
#define K_LOG2 0.49978218f   // log2(1.414)

// flow_y == 0 -> 1-D row splat: pixel x hits bins x0=floor(x-d) and x0+1.
// (c0,c1) and (c2,wsum) accumulate as two __half2 shared planes via
// return-free red.shared.add.noftz.f16x2. 4 REDs/pixel is the exact payload
// floor (8 f16 scalars / 2 per 32-bit RED); RED lane rate pins l1tex busy at
// ~46us, mapping-invariant.
//
// R14: persistent grid (888 blocks = one full wave) with static row
// assignment. 5760 one-row blocks quantize into 6.49 waves (partial 7th wave
// idles ~half the chip) plus wave-transition overhead; persistence converts
// that into a 1-row imbalance. Planes are double-buffered so each row keeps
// R10's two barriers (a buffer is reused only two barriers later).
__device__ __forceinline__ int bhash(int bin) {
    return bin ^ ((bin >> 5) & 28);
}

__device__ __forceinline__ void red_sh_h2(unsigned addr, unsigned val) {
    asm volatile("red.shared.add.noftz.f16x2 [%0], %1;"
                 :: "r"(addr), "r"(val) : "memory");
}

__device__ __forceinline__ unsigned pack_h2(float a, float b) {
    __half2 h = __floats2half2_rn(a, b);
    return *(unsigned*)&h;
}

__global__ __launch_bounds__(320, 6) void splat_kernel(
    const float* __restrict__ im,
    const float* __restrict__ disp,
    float* __restrict__ out)
{
    __shared__ __half2 sA[2][WW];   // (c0, c1), hashed slots, double-buffered
    __shared__ __half2 sB[2][WW];   // (c2, w ), hashed slots

    const int tid = threadIdx.x;
    const int xb  = tid * 4;
    const int g   = (xb ^ ((xb >> 5) & 28)) >> 2;   // readback uint4 index

    int p = 0;
    #pragma unroll 1
    for (int row = blockIdx.x; row < NROWS; row += GRID, p ^= 1) {
        const int b = row / HH;
        const int y = row - b * HH;

        const float4* d_row4 = (const float4*)(disp + (size_t)row * WW);
        const float*  im_row = im  + (size_t)b * CHAN * HW + (size_t)y * WW;
        float*        o_row  = out + (size_t)b * CHAN * HW + (size_t)y * WW;

        const unsigned baseA = (unsigned)__cvta_generic_to_shared(sA[p]);
        const unsigned baseB = (unsigned)__cvta_generic_to_shared(sB[p]);

        // issue global loads first (they overlap the zero phase + barrier)
        float4 d4 = d_row4[tid];
        float4 c0 = ((const float4*)(im_row))[tid];
        float4 c1 = ((const float4*)(im_row + HW))[tid];
        float4 c2 = ((const float4*)(im_row + 2 * HW))[tid];

        // zero buffer p (safe: last touched two barriers ago)
        ((uint4*)sA[p])[tid] = make_uint4(0u, 0u, 0u, 0u);
        ((uint4*)sB[p])[tid] = make_uint4(0u, 0u, 0u, 0u);
        __syncthreads();

        const float dd[4] = {d4.x, d4.y, d4.z, d4.w};
        const float p0[4] = {c0.x, c0.y, c0.z, c0.w};
        const float p1[4] = {c1.x, c1.y, c1.z, c1.w};
        const float p2[4] = {c2.x, c2.y, c2.z, c2.w};

        // precompute payloads/addresses, then fire REDs (no return deps)
        unsigned adrA[8], adrB[8], valA[8], valB[8];
        bool ok[8];
        #pragma unroll
        for (int k = 0; k < 4; k++) {
            float d = dd[k];
            float w;
            asm("ex2.approx.f32 %0, %1;" : "=f"(w) : "f"(d * K_LOG2));
            float tx  = (float)(xb + k) - d;
            int   x0  = __float2int_rd(tx);
            float fc  = tx - (float)x0;   // weight toward x0+1
            float wc  = w * fc;           // combined weight at x0+1
            float wa  = w - wc;           // combined weight at x0

            float v0 = p0[k], v1 = p1[k], v2 = p2[k];

            int h0 = bhash(x0);
            int h1 = bhash(x0 + 1);
            ok[2 * k]     = (unsigned)x0 < WW;        // x0 in [x-21, x]
            ok[2 * k + 1] = (unsigned)(x0 + 1) < WW;
            adrA[2 * k]     = baseA + 4u * h0;
            adrB[2 * k]     = baseB + 4u * h0;
            adrA[2 * k + 1] = baseA + 4u * h1;
            adrB[2 * k + 1] = baseB + 4u * h1;
            valA[2 * k]     = pack_h2(v0 * wa, v1 * wa);
            valB[2 * k]     = pack_h2(v2 * wa, wa);
            valA[2 * k + 1] = pack_h2(v0 * wc, v1 * wc);
            valB[2 * k + 1] = pack_h2(v2 * wc, wc);
        }
        #pragma unroll
        for (int i = 0; i < 8; i++) {
            if (ok[i]) {
                red_sh_h2(adrA[i], valA[i]);
                red_sh_h2(adrB[i], valB[i]);
            }
        }
        __syncthreads();

        // ---- normalize: hash keeps aligned 4-bin groups contiguous ----
        uint4 ua = ((const uint4*)sA[p])[g];
        uint4 ub = ((const uint4*)sB[p])[g];
        const unsigned va[4] = {ua.x, ua.y, ua.z, ua.w};
        const unsigned vb[4] = {ub.x, ub.y, ub.z, ub.w};

        float4 r0, r1, r2;
        float* r0p = &r0.x; float* r1p = &r1.x; float* r2p = &r2.x;
        #pragma unroll
        for (int j = 0; j < 4; j++) {
            __half2 a  = *(const __half2*)&va[j];
            __half2 bb = *(const __half2*)&vb[j];
            float n0 = __low2float(a),  n1 = __high2float(a);
            float n2 = __low2float(bb), ws = __high2float(bb);
            float inv;
            asm("rcp.approx.f32 %0, %1;" : "=f"(inv) : "f"(fmaxf(ws, EPSV)));
            r0p[j] = n0 * inv;
            r1p[j] = n1 * inv;
            r2p[j] = n2 * inv;
        }
        ((float4*)o_row)[tid]            = r0;
        ((float4*)(o_row + HW))[tid]     = r1;
        ((float4*)(o_row + 2 * HW))[tid] = r2;
        // no third barrier: next iteration uses buffer p^1; buffer p is
        // reused only after two more barriers.
    }
}

extern "C" void kernel_launch(void* const* d_in, const int* in_sizes, int n_in,
                              void* d_out, int out_size) {
    const float* im   = (const float*)d_in[0];   // [8,3,720,1280] fp32
    const float* disp = (const float*)d_in[1];   // [8,1,720,1280] fp32
    float* out = (float*)d_out;                  // [8,3,720,1280] fp32

    splat_kernel<<<GRID, 320>>>(im, disp, out);
}

// round 15
// speedup vs baseline: 1.0342x; 1.0303x over previous
#include <cuda_runtime.h>
#include <cuda_fp16.h>

// Problem shape (fixed by the dataset)
#define BATCH 8
#define CHAN  3
#define HH    720
#define WW    1280
#define HW    (HH * WW)
#define NROWS (BATCH * HH)
#define EPSV  1e-6f
#define K_LOG2 0.49978218f     // log2(1.414)

// flow_y == 0 -> 1-D row splat: pixel x hits bins x0=floor(x-d) and x0+1.
// (c0,c1) and (c2,wsum) accumulate as two __half2 shared planes via
// return-free red.shared.add.noftz.f16x2 (4 REDs/px = exact payload floor;
// RED warp-instr cost ~12cyc is address-entropy-bound, mapping-invariant).
// One row per 320-thread block: four structural alternatives (row batching,
// persistence, 256-thr) all regressed -> plain launch is optimal.
//
// R15: dependency reorder. disp + c2 load first so the sB-plane REDs
// (needing only w,c2) fire while c0,c1 are still in flight; predicates
// inlined so ptxas can software-pipeline the burst.
__device__ __forceinline__ int bhash(int bin) {
    return bin ^ ((bin >> 5) & 28);
}

__device__ __forceinline__ void red_sh_h2(unsigned addr, unsigned val) {
    asm volatile("red.shared.add.noftz.f16x2 [%0], %1;"
                 :: "r"(addr), "r"(val) : "memory");
}

__device__ __forceinline__ unsigned pack_h2(float a, float b) {
    __half2 h = __floats2half2_rn(a, b);
    return *(unsigned*)&h;
}

__global__ __launch_bounds__(320) void splat_kernel(
    const float* __restrict__ im,
    const float* __restrict__ disp,
    float* __restrict__ out)
{
    __shared__ __half2 sA[WW];   // (c0, c1), hashed slots
    __shared__ __half2 sB[WW];   // (c2, w ), hashed slots

    const int row = blockIdx.x;      // b*HH + y
    const int b   = row / HH;
    const int y   = row - b * HH;
    const int tid = threadIdx.x;

    const unsigned baseA = (unsigned)__cvta_generic_to_shared(sA);
    const unsigned baseB = (unsigned)__cvta_generic_to_shared(sB);

    const float* d_row  = disp + (size_t)row * WW;
    const float* im_row = im  + (size_t)b * CHAN * HW + (size_t)y * WW;
    float*       o_row  = out + (size_t)b * CHAN * HW + (size_t)y * WW;

    // issue d and c2 first: the sB REDs depend only on these
    float4 d4 = ((const float4*)d_row)[tid];
    float4 c2 = ((const float4*)(im_row + 2 * HW))[tid];
    float4 c0 = ((const float4*)(im_row))[tid];
    float4 c1 = ((const float4*)(im_row + HW))[tid];

    // ---- zero both planes (overlaps the loads above) ----
    ((uint4*)sA)[tid] = make_uint4(0u, 0u, 0u, 0u);
    ((uint4*)sB)[tid] = make_uint4(0u, 0u, 0u, 0u);
    __syncthreads();

    const int xb = tid * 4;
    const float dd[4] = {d4.x, d4.y, d4.z, d4.w};
    const float p2[4] = {c2.x, c2.y, c2.z, c2.w};

    // per-pixel geometry (depends on d only)
    unsigned hs0[4], hs1[4];
    bool ok0[4], ok1[4];
    float WA[4], WC[4];
    #pragma unroll
    for (int k = 0; k < 4; k++) {
        float d = dd[k];
        float w;
        asm("ex2.approx.f32 %0, %1;" : "=f"(w) : "f"(d * K_LOG2));
        float tx  = (float)(xb + k) - d;
        int   x0  = __float2int_rd(tx);
        float fc  = tx - (float)x0;
        WC[k] = w * fc;           // weight at x0+1
        WA[k] = w - WC[k];        // weight at x0
        ok0[k] = (unsigned)x0 < WW;
        ok1[k] = (unsigned)(x0 + 1) < WW;
        hs0[k] = 4u * bhash(x0);
        hs1[k] = 4u * bhash(x0 + 1);
    }

    // sB REDs first: need only c2 + geometry (c0/c1 may still be in flight)
    #pragma unroll
    for (int k = 0; k < 4; k++) {
        if (ok0[k]) red_sh_h2(baseB + hs0[k], pack_h2(p2[k] * WA[k], WA[k]));
        if (ok1[k]) red_sh_h2(baseB + hs1[k], pack_h2(p2[k] * WC[k], WC[k]));
    }

    const float p0[4] = {c0.x, c0.y, c0.z, c0.w};
    const float p1[4] = {c1.x, c1.y, c1.z, c1.w};

    // sA REDs
    #pragma unroll
    for (int k = 0; k < 4; k++) {
        if (ok0[k]) red_sh_h2(baseA + hs0[k],
                              pack_h2(p0[k] * WA[k], p1[k] * WA[k]));
        if (ok1[k]) red_sh_h2(baseA + hs1[k],
                              pack_h2(p0[k] * WC[k], p1[k] * WC[k]));
    }
    __syncthreads();

    // ---- normalize: hash keeps aligned 4-bin groups contiguous/ordered ----
    const int g = (xb ^ ((xb >> 5) & 28)) >> 2;
    uint4 ua = ((const uint4*)sA)[g];
    uint4 ub = ((const uint4*)sB)[g];
    const unsigned va[4] = {ua.x, ua.y, ua.z, ua.w};
    const unsigned vb[4] = {ub.x, ub.y, ub.z, ub.w};

    float4 r0, r1, r2;
    float* r0p = &r0.x; float* r1p = &r1.x; float* r2p = &r2.x;
    #pragma unroll
    for (int j = 0; j < 4; j++) {
        __half2 a  = *(const __half2*)&va[j];
        __half2 bb = *(const __half2*)&vb[j];
        float n0 = __low2float(a),  n1 = __high2float(a);
        float n2 = __low2float(bb), ws = __high2float(bb);
        float inv;
        asm("rcp.approx.f32 %0, %1;" : "=f"(inv) : "f"(fmaxf(ws, EPSV)));
        r0p[j] = n0 * inv;
        r1p[j] = n1 * inv;
        r2p[j] = n2 * inv;
    }
    ((float4*)o_row)[tid]            = r0;
    ((float4*)(o_row + HW))[tid]     = r1;
    ((float4*)(o_row + 2 * HW))[tid] = r2;
}

extern "C" void kernel_launch(void* const* d_in, const int* in_sizes, int n_in,
                              void* d_out, int out_size) {
    const float* im   = (const float*)d_in[0];   // [8,3,720,1280] fp32
    const float* disp = (const float*)d_in[1];   // [8,1,720,1280] fp32
    float* out = (float*)d_out;                  // [8,3,720,1280] fp32

    splat_kernel<<<NROWS, 320>>>(im, disp, out);
}